// round 1
// baseline (speedup 1.0000x reference)
#include <cuda_runtime.h>
#include <math.h>

// Problem constants
#define BATCH 8
#define NH    8       // heads
#define SEQQ  1024
#define SEQK  1024
#define DIM   512
#define HD    64      // head dim
#define MROWS (BATCH*SEQQ)   // 8192

static __device__ float g_q [BATCH*SEQQ*DIM];
static __device__ float g_k [BATCH*SEQK*DIM];
static __device__ float g_v [BATCH*SEQK*DIM];
static __device__ float g_t0[BATCH*SEQQ*DIM];
static __device__ float g_t1[BATCH*SEQQ*DIM];
static __device__ float g_s [(long)BATCH*NH*SEQQ*SEQK];   // 256 MB logits

#define EPI_BIAS       0
#define EPI_MASK       1
#define EPI_RESID      2
#define EPI_RELU_RESID 3

#define LN_EPS   1e-5f
#define MASK_INF 1e38f

// ---------------------------------------------------------------------------
// Generic tiled fp32 GEMM.  C = A @ B (or A @ B^T if TB), with epilogues.
// Batched over blockIdx.z: offset = (z/NH)*s?b + (z%NH)*s?h.
// Residual R (if used) shares C's ld and offsets.
// All dims assumed exact multiples of tile sizes (true for this problem).
// ---------------------------------------------------------------------------
template<int BM,int BN,int BK,int TM,int TN,bool TB,int EPI>
__global__ __launch_bounds__((BM/TM)*(BN/TN))
void gemm_k(const float* __restrict__ A, int lda, long sAb, long sAh,
            const float* __restrict__ B, int ldb, long sBb, long sBh,
            float*       __restrict__ C, int ldc, long sCb, long sCh,
            int K,
            const float* __restrict__ bias,
            const float* __restrict__ R,
            const float* __restrict__ pq,
            const float* __restrict__ pk,
            float scale)
{
    constexpr int THREADS = (BM/TM)*(BN/TN);
    __shared__ float As[BK][BM];
    __shared__ float Bs[BK][BN];

    const int z  = blockIdx.z;
    const int bz = z / NH;
    const int hz = z - bz*NH;
    A += (long)bz*sAb + (long)hz*sAh;
    B += (long)bz*sBb + (long)hz*sBh;
    C += (long)bz*sCb + (long)hz*sCh;
    const float* Rp = R ? (R + (long)bz*sCb + (long)hz*sCh) : (const float*)0;

    const int m0 = blockIdx.y * BM;
    const int n0 = blockIdx.x * BN;
    const int tid = threadIdx.x;
    const int tx  = tid % (BN/TN);
    const int ty  = tid / (BN/TN);
    const int row0 = ty * TM;
    const int col0 = tx * TN;

    float acc[TM][TN];
    #pragma unroll
    for (int i = 0; i < TM; i++)
        #pragma unroll
        for (int j = 0; j < TN; j++) acc[i][j] = 0.f;

    for (int k0 = 0; k0 < K; k0 += BK) {
        // --- load A tile (BM x BK), stored transposed As[k][m]
        #pragma unroll
        for (int r = 0; r < (BM*BK)/THREADS; r++) {
            int i = tid + r*THREADS;
            int m = i / BK, kk = i % BK;
            As[kk][m] = A[(long)(m0+m)*lda + (k0+kk)];
        }
        // --- load B tile (BK x BN) -> Bs[k][n]
        #pragma unroll
        for (int r = 0; r < (BK*BN)/THREADS; r++) {
            int i = tid + r*THREADS;
            if (TB) { int n = i / BK, kk = i % BK;
                      Bs[kk][n] = B[(long)(n0+n)*ldb + (k0+kk)]; }
            else    { int kk = i / BN, n = i % BN;
                      Bs[kk][n] = B[(long)(k0+kk)*ldb + (n0+n)]; }
        }
        __syncthreads();

        #pragma unroll
        for (int kk = 0; kk < BK; kk++) {
            float a[TM], b[TN];
            #pragma unroll
            for (int i = 0; i < TM; i++) a[i] = As[kk][row0+i];
            #pragma unroll
            for (int j = 0; j < TN; j++) b[j] = Bs[kk][col0+j];
            #pragma unroll
            for (int i = 0; i < TM; i++)
                #pragma unroll
                for (int j = 0; j < TN; j++)
                    acc[i][j] = fmaf(a[i], b[j], acc[i][j]);
        }
        __syncthreads();
    }

    // --- epilogue
    #pragma unroll
    for (int i = 0; i < TM; i++) {
        const int m = m0 + row0 + i;
        #pragma unroll
        for (int j = 0; j < TN; j++) {
            const int n = n0 + col0 + j;
            float v = acc[i][j];
            if (EPI == EPI_BIAS) {
                v += bias[n];
            } else if (EPI == EPI_MASK) {
                v *= scale;
                const float pqv = pq[bz*SEQQ + m];
                const float pkv = pk[bz*SEQK + n];
                v = pqv*v - (1.f - pqv)*MASK_INF;
                v = pkv*v - (1.f - pkv)*MASK_INF;
            } else if (EPI == EPI_RESID) {
                v += Rp[(long)m*ldc + n];
            } else if (EPI == EPI_RELU_RESID) {
                v = Rp[(long)m*ldc + n] + fmaxf(v + bias[n], 0.f);
            }
            C[(long)m*ldc + n] = v;
        }
    }
}

// ---------------------------------------------------------------------------
// Row softmax over SEQK=1024 columns. One block (256 threads) per row.
// ---------------------------------------------------------------------------
__global__ __launch_bounds__(256)
void softmax_k(float* __restrict__ S)
{
    float* p = S + (long)blockIdx.x * SEQK;
    const int tid = threadIdx.x;
    const int w = tid >> 5, l = tid & 31;
    __shared__ float smax[8];
    __shared__ float ssum[8];

    float v[4];
    #pragma unroll
    for (int i = 0; i < 4; i++) v[i] = p[tid + i*256];

    float m = fmaxf(fmaxf(v[0],v[1]), fmaxf(v[2],v[3]));
    #pragma unroll
    for (int o = 16; o > 0; o >>= 1) m = fmaxf(m, __shfl_xor_sync(0xffffffffu, m, o));
    if (l == 0) smax[w] = m;
    __syncthreads();
    float bm = smax[0];
    #pragma unroll
    for (int i = 1; i < 8; i++) bm = fmaxf(bm, smax[i]);

    float s = 0.f;
    #pragma unroll
    for (int i = 0; i < 4; i++) { v[i] = __expf(v[i] - bm); s += v[i]; }
    #pragma unroll
    for (int o = 16; o > 0; o >>= 1) s += __shfl_xor_sync(0xffffffffu, s, o);
    if (l == 0) ssum[w] = s;
    __syncthreads();
    float tot = 0.f;
    #pragma unroll
    for (int i = 0; i < 8; i++) tot += ssum[i];

    const float inv = 1.f / tot;
    #pragma unroll
    for (int i = 0; i < 4; i++) p[tid + i*256] = v[i] * inv;
}

// ---------------------------------------------------------------------------
// LayerNorm over last dim (512). One block (128 threads) per row.
// ---------------------------------------------------------------------------
__global__ __launch_bounds__(128)
void ln_k(const float* __restrict__ X, float* __restrict__ Y,
          const float* __restrict__ gamma, const float* __restrict__ beta)
{
    const long row = blockIdx.x;
    const float* x = X + row*DIM;
    const int tid = threadIdx.x;
    const int w = tid >> 5, l = tid & 31;
    __shared__ float sred[4];

    float v[4];
    #pragma unroll
    for (int i = 0; i < 4; i++) v[i] = x[tid + i*128];

    float s = v[0]+v[1]+v[2]+v[3];
    #pragma unroll
    for (int o = 16; o > 0; o >>= 1) s += __shfl_xor_sync(0xffffffffu, s, o);
    if (l == 0) sred[w] = s;
    __syncthreads();
    float mu = (sred[0]+sred[1]+sred[2]+sred[3]) * (1.f/DIM);
    __syncthreads();

    float sq = 0.f;
    #pragma unroll
    for (int i = 0; i < 4; i++) { v[i] -= mu; sq += v[i]*v[i]; }
    #pragma unroll
    for (int o = 16; o > 0; o >>= 1) sq += __shfl_xor_sync(0xffffffffu, sq, o);
    if (l == 0) sred[w] = sq;
    __syncthreads();
    const float var = (sred[0]+sred[1]+sred[2]+sred[3]) * (1.f/DIM);
    const float r = rsqrtf(var + LN_EPS);

    #pragma unroll
    for (int i = 0; i < 4; i++) {
        const int c = tid + i*128;
        Y[row*DIM + c] = v[i]*r*gamma[c] + beta[c];
    }
}

// ---------------------------------------------------------------------------
extern "C" void kernel_launch(void* const* d_in, const int* in_sizes, int n_in,
                              void* d_out, int out_size)
{
    (void)in_sizes; (void)n_in; (void)out_size;
    const float* queries = (const float*)d_in[0];
    const float* keys    = (const float*)d_in[1];
    const float* pq      = (const float*)d_in[2];
    const float* pk      = (const float*)d_in[3];
    // d_in[4] = num_heads (int scalar) — fixed to 8
    const float* Wq = (const float*)d_in[5];
    const float* bq = (const float*)d_in[6];
    const float* Wk = (const float*)d_in[7];
    const float* bk = (const float*)d_in[8];
    const float* Wv = (const float*)d_in[9];
    const float* bv = (const float*)d_in[10];
    const float* Wo = (const float*)d_in[11];
    const float* bo = (const float*)d_in[12];
    const float* g0 = (const float*)d_in[13];
    const float* b0 = (const float*)d_in[14];
    const float* g1 = (const float*)d_in[15];
    const float* b1 = (const float*)d_in[16];
    float* out = (float*)d_out;

    float *q, *k, *v, *s, *t0, *t1;
    cudaGetSymbolAddress((void**)&q,  g_q);
    cudaGetSymbolAddress((void**)&k,  g_k);
    cudaGetSymbolAddress((void**)&v,  g_v);
    cudaGetSymbolAddress((void**)&s,  g_s);
    cudaGetSymbolAddress((void**)&t0, g_t0);
    cudaGetSymbolAddress((void**)&t1, g_t1);

    const float att_scale = 1.0f / sqrtf((float)DIM);

    // --- projections: q/k/v = X @ W + b   (8192x512 @ 512x512)
    {
        dim3 grid(DIM/128, MROWS/128, 1);
        gemm_k<128,128,8,8,8,false,EPI_BIAS><<<grid,256>>>(
            queries,DIM,0,0,  Wq,DIM,0,0,  q,DIM,0,0,  DIM, bq, 0, 0,0, 0.f);
        gemm_k<128,128,8,8,8,false,EPI_BIAS><<<grid,256>>>(
            keys,DIM,0,0,     Wk,DIM,0,0,  k,DIM,0,0,  DIM, bk, 0, 0,0, 0.f);
        gemm_k<128,128,8,8,8,false,EPI_BIAS><<<grid,256>>>(
            keys,DIM,0,0,     Wv,DIM,0,0,  v,DIM,0,0,  DIM, bv, 0, 0,0, 0.f);
    }

    // --- logits: S[b,h] = (Qh @ Kh^T) * scale, masked  (1024x1024, K=64) x64
    {
        dim3 grid(SEQK/128, SEQQ/128, BATCH*NH);
        gemm_k<128,128,8,8,8,true,EPI_MASK><<<grid,256>>>(
            q, DIM, (long)SEQQ*DIM, HD,
            k, DIM, (long)SEQK*DIM, HD,
            s, SEQK, (long)NH*SEQQ*SEQK, (long)SEQQ*SEQK,
            HD, 0, 0, pq, pk, att_scale);
    }

    // --- softmax rows
    softmax_k<<<BATCH*NH*SEQQ, 256>>>(s);

    // --- O[b,h] = qh + A @ Vh  (1024x64, K=1024) x64
    {
        dim3 grid(HD/64, SEQQ/128, BATCH*NH);
        gemm_k<128,64,8,8,4,false,EPI_RESID><<<grid,256>>>(
            s, SEQK, (long)NH*SEQQ*SEQK, (long)SEQQ*SEQK,
            v, DIM, (long)SEQK*DIM, HD,
            t0, DIM, (long)SEQQ*DIM, HD,
            SEQK, 0, q, 0,0, 0.f);
    }

    // --- LN0 (in place)
    ln_k<<<MROWS, 128>>>(t0, t0, g0, b0);

    // --- t1 = t0 + relu(t0 @ Wo + bo)
    {
        dim3 grid(DIM/128, MROWS/128, 1);
        gemm_k<128,128,8,8,8,false,EPI_RELU_RESID><<<grid,256>>>(
            t0,DIM,0,0,  Wo,DIM,0,0,  t1,DIM,0,0,  DIM, bo, t0, 0,0, 0.f);
    }

    // --- LN1 -> out
    ln_k<<<MROWS, 128>>>(t1, out, g1, b1);
}

// round 2
// speedup vs baseline: 2.6521x; 2.6521x over previous
#include <cuda_runtime.h>
#include <math.h>

// Problem constants
#define BATCH 8
#define NH    8
#define SEQQ  1024
#define SEQK  1024
#define DIM   512
#define HD    64
#define MROWS (BATCH*SEQQ)   // 8192

#define LN_EPS   1e-5f
#define MASK_INF 1e38f

#define EPI_BIAS       0
#define EPI_RELU_RESID 3

static __device__ float g_q [BATCH*SEQQ*DIM];
static __device__ float g_k [BATCH*SEQK*DIM];
static __device__ float g_v [BATCH*SEQK*DIM];
static __device__ float g_t0[BATCH*SEQQ*DIM];
static __device__ float g_t1[BATCH*SEQQ*DIM];
static __device__ float g_s [(long)BATCH*NH*SEQQ*SEQK];   // 256 MB logits

// ---------------------------------------------------------------------------
// tf32 helpers
// ---------------------------------------------------------------------------
__device__ __forceinline__ unsigned f2tf(float x) {
    unsigned u;
    asm("cvt.rna.tf32.f32 %0, %1;" : "=r"(u) : "f"(x));
    return u;
}

__device__ __forceinline__ void mma_tf32(float* c, const unsigned* a, const unsigned* b) {
    asm volatile(
        "mma.sync.aligned.m16n8k8.row.col.f32.tf32.tf32.f32 "
        "{%0,%1,%2,%3},{%4,%5,%6,%7},{%8,%9},{%0,%1,%2,%3};"
        : "+f"(c[0]), "+f"(c[1]), "+f"(c[2]), "+f"(c[3])
        : "r"(a[0]), "r"(a[1]), "r"(a[2]), "r"(a[3]), "r"(b[0]), "r"(b[1]));
}

// ---------------------------------------------------------------------------
// Dense NN GEMM: C[M,N] = A[M,K] @ B[K,N] + epilogue. BM=128,BN=128,BK=16.
// 8 warps: 4(m) x 2(n); warp tile 32x64. Requires M%128==0, N%128==0, K%16==0.
// ---------------------------------------------------------------------------
template<int EPI>
__global__ __launch_bounds__(256)
void gemm_nn_tc(const float* __restrict__ A, const float* __restrict__ B,
                float* __restrict__ C, int M, int N, int K,
                const float* __restrict__ bias, const float* __restrict__ R)
{
    __shared__ unsigned As[128][20];   // [m][k], tf32 bits
    __shared__ unsigned Bs[16][136];   // [k][n], tf32 bits (8-word skew)

    const int tid  = threadIdx.x;
    const int m0   = blockIdx.y * 128;
    const int n0   = blockIdx.x * 128;
    const int lane = tid & 31;
    const int warp = tid >> 5;
    const int g    = lane >> 2;
    const int q    = lane & 3;
    const int mBase = (warp & 3) * 32;
    const int nBase = (warp >> 2) * 64;

    float acc[2][8][4];
    #pragma unroll
    for (int i = 0; i < 2; i++)
        #pragma unroll
        for (int j = 0; j < 8; j++)
            #pragma unroll
            for (int r = 0; r < 4; r++) acc[i][j][r] = 0.f;

    for (int k0 = 0; k0 < K; k0 += 16) {
        #pragma unroll
        for (int r = 0; r < 2; r++) {
            int f = tid + r * 256;            // 0..511
            int m = f >> 2, kq = (f & 3) << 2;
            float4 t = *(const float4*)(A + (size_t)(m0 + m) * K + k0 + kq);
            As[m][kq+0] = f2tf(t.x); As[m][kq+1] = f2tf(t.y);
            As[m][kq+2] = f2tf(t.z); As[m][kq+3] = f2tf(t.w);
        }
        #pragma unroll
        for (int r = 0; r < 2; r++) {
            int f = tid + r * 256;
            int kk = f >> 5, nc = (f & 31) << 2;
            float4 t = *(const float4*)(B + (size_t)(k0 + kk) * N + n0 + nc);
            Bs[kk][nc+0] = f2tf(t.x); Bs[kk][nc+1] = f2tf(t.y);
            Bs[kk][nc+2] = f2tf(t.z); Bs[kk][nc+3] = f2tf(t.w);
        }
        __syncthreads();

        #pragma unroll
        for (int ks = 0; ks < 16; ks += 8) {
            unsigned a[2][4], b[8][2];
            #pragma unroll
            for (int i = 0; i < 2; i++) {
                int row = mBase + i * 16 + g;
                a[i][0] = As[row    ][ks + q];
                a[i][1] = As[row + 8][ks + q];
                a[i][2] = As[row    ][ks + q + 4];
                a[i][3] = As[row + 8][ks + q + 4];
            }
            #pragma unroll
            for (int j = 0; j < 8; j++) {
                int col = nBase + j * 8 + g;
                b[j][0] = Bs[ks + q    ][col];
                b[j][1] = Bs[ks + q + 4][col];
            }
            #pragma unroll
            for (int i = 0; i < 2; i++)
                #pragma unroll
                for (int j = 0; j < 8; j++)
                    mma_tf32(acc[i][j], a[i], b[j]);
        }
        __syncthreads();
    }

    #pragma unroll
    for (int i = 0; i < 2; i++) {
        #pragma unroll
        for (int rr = 0; rr < 2; rr++) {
            int row = m0 + mBase + i * 16 + g + rr * 8;
            #pragma unroll
            for (int j = 0; j < 8; j++) {
                int col = n0 + nBase + j * 8 + 2 * q;
                float v0 = acc[i][j][rr*2 + 0];
                float v1 = acc[i][j][rr*2 + 1];
                if (EPI == EPI_BIAS) {
                    v0 += bias[col]; v1 += bias[col + 1];
                } else { // EPI_RELU_RESID
                    v0 = R[(size_t)row*N + col    ] + fmaxf(v0 + bias[col    ], 0.f);
                    v1 = R[(size_t)row*N + col + 1] + fmaxf(v1 + bias[col + 1], 0.f);
                }
                *(float2*)(C + (size_t)row * N + col) = make_float2(v0, v1);
            }
        }
    }
}

// ---------------------------------------------------------------------------
// Logits: S[z] = mask(scale * Qh @ Kh^T). z = b*NH + h. BM=BN=128, K=64.
// ---------------------------------------------------------------------------
__global__ __launch_bounds__(256)
void logits_tc(const float* __restrict__ Qm, const float* __restrict__ Km,
               float* __restrict__ S,
               const float* __restrict__ pq, const float* __restrict__ pk,
               float scale)
{
    __shared__ unsigned As [128][20];  // [m][k]
    __shared__ unsigned BsT[128][20];  // [n][k]

    const int z  = blockIdx.z;
    const int bz = z >> 3;
    const int hz = z & 7;
    const float* A = Qm + (size_t)bz * SEQQ * DIM + hz * HD;
    const float* B = Km + (size_t)bz * SEQK * DIM + hz * HD;
    float* Sp = S + (size_t)z * SEQQ * SEQK;

    const int tid  = threadIdx.x;
    const int m0   = blockIdx.y * 128;
    const int n0   = blockIdx.x * 128;
    const int lane = tid & 31;
    const int warp = tid >> 5;
    const int g    = lane >> 2;
    const int q    = lane & 3;
    const int mBase = (warp & 3) * 32;
    const int nBase = (warp >> 2) * 64;

    float acc[2][8][4];
    #pragma unroll
    for (int i = 0; i < 2; i++)
        #pragma unroll
        for (int j = 0; j < 8; j++)
            #pragma unroll
            for (int r = 0; r < 4; r++) acc[i][j][r] = 0.f;

    #pragma unroll
    for (int k0 = 0; k0 < HD; k0 += 16) {
        #pragma unroll
        for (int r = 0; r < 2; r++) {
            int f = tid + r * 256;
            int m = f >> 2, kq = (f & 3) << 2;
            float4 t = *(const float4*)(A + (size_t)(m0 + m) * DIM + k0 + kq);
            As[m][kq+0] = f2tf(t.x); As[m][kq+1] = f2tf(t.y);
            As[m][kq+2] = f2tf(t.z); As[m][kq+3] = f2tf(t.w);
        }
        #pragma unroll
        for (int r = 0; r < 2; r++) {
            int f = tid + r * 256;
            int n = f >> 2, kq = (f & 3) << 2;
            float4 t = *(const float4*)(B + (size_t)(n0 + n) * DIM + k0 + kq);
            BsT[n][kq+0] = f2tf(t.x); BsT[n][kq+1] = f2tf(t.y);
            BsT[n][kq+2] = f2tf(t.z); BsT[n][kq+3] = f2tf(t.w);
        }
        __syncthreads();

        #pragma unroll
        for (int ks = 0; ks < 16; ks += 8) {
            unsigned a[2][4], b[8][2];
            #pragma unroll
            for (int i = 0; i < 2; i++) {
                int row = mBase + i * 16 + g;
                a[i][0] = As[row    ][ks + q];
                a[i][1] = As[row + 8][ks + q];
                a[i][2] = As[row    ][ks + q + 4];
                a[i][3] = As[row + 8][ks + q + 4];
            }
            #pragma unroll
            for (int j = 0; j < 8; j++) {
                int col = nBase + j * 8 + g;
                b[j][0] = BsT[col][ks + q];
                b[j][1] = BsT[col][ks + q + 4];
            }
            #pragma unroll
            for (int i = 0; i < 2; i++)
                #pragma unroll
                for (int j = 0; j < 8; j++)
                    mma_tf32(acc[i][j], a[i], b[j]);
        }
        __syncthreads();
    }

    #pragma unroll
    for (int i = 0; i < 2; i++) {
        #pragma unroll
        for (int rr = 0; rr < 2; rr++) {
            int row = m0 + mBase + i * 16 + g + rr * 8;
            const float pqv = pq[bz * SEQQ + row];
            #pragma unroll
            for (int j = 0; j < 8; j++) {
                int col = n0 + nBase + j * 8 + 2 * q;
                float v0 = acc[i][j][rr*2 + 0] * scale;
                float v1 = acc[i][j][rr*2 + 1] * scale;
                const float pk0 = pk[bz * SEQK + col];
                const float pk1 = pk[bz * SEQK + col + 1];
                v0 = pqv * v0 - (1.f - pqv) * MASK_INF;
                v1 = pqv * v1 - (1.f - pqv) * MASK_INF;
                v0 = pk0 * v0 - (1.f - pk0) * MASK_INF;
                v1 = pk1 * v1 - (1.f - pk1) * MASK_INF;
                *(float2*)(Sp + (size_t)row * SEQK + col) = make_float2(v0, v1);
            }
        }
    }
}

// ---------------------------------------------------------------------------
// A@V + q residual: O[z rows] = qh + S[z] @ Vh. BM=128, BN=64, K=1024.
// 8 warps: 4(m) x 2(n); warp tile 32x32.
// ---------------------------------------------------------------------------
__global__ __launch_bounds__(256)
void av_tc(const float* __restrict__ S, const float* __restrict__ V,
           const float* __restrict__ Qh, float* __restrict__ O)
{
    __shared__ unsigned As[128][20];   // [m][k]  (S tile)
    __shared__ unsigned Bs[16][72];    // [k][n]  (V tile, 8-word skew)

    const int z  = blockIdx.z;
    const int bz = z >> 3;
    const int hz = z & 7;
    const float* A = S + (size_t)z * SEQQ * SEQK;
    const float* B = V + (size_t)bz * SEQK * DIM + hz * HD;

    const int tid  = threadIdx.x;
    const int m0   = blockIdx.y * 128;
    const int lane = tid & 31;
    const int warp = tid >> 5;
    const int g    = lane >> 2;
    const int q    = lane & 3;
    const int mBase = (warp & 3) * 32;
    const int nBase = (warp >> 2) * 32;

    float acc[2][4][4];
    #pragma unroll
    for (int i = 0; i < 2; i++)
        #pragma unroll
        for (int j = 0; j < 4; j++)
            #pragma unroll
            for (int r = 0; r < 4; r++) acc[i][j][r] = 0.f;

    for (int k0 = 0; k0 < SEQK; k0 += 16) {
        #pragma unroll
        for (int r = 0; r < 2; r++) {
            int f = tid + r * 256;
            int m = f >> 2, kq = (f & 3) << 2;
            float4 t = *(const float4*)(A + (size_t)(m0 + m) * SEQK + k0 + kq);
            As[m][kq+0] = f2tf(t.x); As[m][kq+1] = f2tf(t.y);
            As[m][kq+2] = f2tf(t.z); As[m][kq+3] = f2tf(t.w);
        }
        {
            int kk = tid >> 4, nc = (tid & 15) << 2;
            float4 t = *(const float4*)(B + (size_t)(k0 + kk) * DIM + nc);
            Bs[kk][nc+0] = f2tf(t.x); Bs[kk][nc+1] = f2tf(t.y);
            Bs[kk][nc+2] = f2tf(t.z); Bs[kk][nc+3] = f2tf(t.w);
        }
        __syncthreads();

        #pragma unroll
        for (int ks = 0; ks < 16; ks += 8) {
            unsigned a[2][4], b[4][2];
            #pragma unroll
            for (int i = 0; i < 2; i++) {
                int row = mBase + i * 16 + g;
                a[i][0] = As[row    ][ks + q];
                a[i][1] = As[row + 8][ks + q];
                a[i][2] = As[row    ][ks + q + 4];
                a[i][3] = As[row + 8][ks + q + 4];
            }
            #pragma unroll
            for (int j = 0; j < 4; j++) {
                int col = nBase + j * 8 + g;
                b[j][0] = Bs[ks + q    ][col];
                b[j][1] = Bs[ks + q + 4][col];
            }
            #pragma unroll
            for (int i = 0; i < 2; i++)
                #pragma unroll
                for (int j = 0; j < 4; j++)
                    mma_tf32(acc[i][j], a[i], b[j]);
        }
        __syncthreads();
    }

    #pragma unroll
    for (int i = 0; i < 2; i++) {
        #pragma unroll
        for (int rr = 0; rr < 2; rr++) {
            int mrow = m0 + mBase + i * 16 + g + rr * 8;
            size_t base = (size_t)(bz * SEQQ + mrow) * DIM + hz * HD;
            #pragma unroll
            for (int j = 0; j < 4; j++) {
                int col = nBase + j * 8 + 2 * q;
                float v0 = acc[i][j][rr*2 + 0] + Qh[base + col];
                float v1 = acc[i][j][rr*2 + 1] + Qh[base + col + 1];
                *(float2*)(O + base + col) = make_float2(v0, v1);
            }
        }
    }
}

// ---------------------------------------------------------------------------
// Row softmax over SEQK=1024 columns. One block (256 threads) per row.
// ---------------------------------------------------------------------------
__global__ __launch_bounds__(256)
void softmax_k(float* __restrict__ S)
{
    float* p = S + (long)blockIdx.x * SEQK;
    const int tid = threadIdx.x;
    const int w = tid >> 5, l = tid & 31;
    __shared__ float smax[8];
    __shared__ float ssum[8];

    float v[4];
    #pragma unroll
    for (int i = 0; i < 4; i++) v[i] = p[tid + i*256];

    float m = fmaxf(fmaxf(v[0],v[1]), fmaxf(v[2],v[3]));
    #pragma unroll
    for (int o = 16; o > 0; o >>= 1) m = fmaxf(m, __shfl_xor_sync(0xffffffffu, m, o));
    if (l == 0) smax[w] = m;
    __syncthreads();
    float bm = smax[0];
    #pragma unroll
    for (int i = 1; i < 8; i++) bm = fmaxf(bm, smax[i]);

    float s = 0.f;
    #pragma unroll
    for (int i = 0; i < 4; i++) { v[i] = __expf(v[i] - bm); s += v[i]; }
    #pragma unroll
    for (int o = 16; o > 0; o >>= 1) s += __shfl_xor_sync(0xffffffffu, s, o);
    if (l == 0) ssum[w] = s;
    __syncthreads();
    float tot = 0.f;
    #pragma unroll
    for (int i = 0; i < 8; i++) tot += ssum[i];

    const float inv = 1.f / tot;
    #pragma unroll
    for (int i = 0; i < 4; i++) p[tid + i*256] = v[i] * inv;
}

// ---------------------------------------------------------------------------
// LayerNorm over last dim (512). One block (128 threads) per row.
// ---------------------------------------------------------------------------
__global__ __launch_bounds__(128)
void ln_k(const float* __restrict__ X, float* __restrict__ Y,
          const float* __restrict__ gamma, const float* __restrict__ beta)
{
    const long row = blockIdx.x;
    const float* x = X + row*DIM;
    const int tid = threadIdx.x;
    const int w = tid >> 5, l = tid & 31;
    __shared__ float sred[4];

    float v[4];
    #pragma unroll
    for (int i = 0; i < 4; i++) v[i] = x[tid + i*128];

    float s = v[0]+v[1]+v[2]+v[3];
    #pragma unroll
    for (int o = 16; o > 0; o >>= 1) s += __shfl_xor_sync(0xffffffffu, s, o);
    if (l == 0) sred[w] = s;
    __syncthreads();
    float mu = (sred[0]+sred[1]+sred[2]+sred[3]) * (1.f/DIM);
    __syncthreads();

    float sq = 0.f;
    #pragma unroll
    for (int i = 0; i < 4; i++) { v[i] -= mu; sq += v[i]*v[i]; }
    #pragma unroll
    for (int o = 16; o > 0; o >>= 1) sq += __shfl_xor_sync(0xffffffffu, sq, o);
    if (l == 0) sred[w] = sq;
    __syncthreads();
    const float var = (sred[0]+sred[1]+sred[2]+sred[3]) * (1.f/DIM);
    const float r = rsqrtf(var + LN_EPS);

    #pragma unroll
    for (int i = 0; i < 4; i++) {
        const int c = tid + i*128;
        Y[row*DIM + c] = v[i]*r*gamma[c] + beta[c];
    }
}

// ---------------------------------------------------------------------------
extern "C" void kernel_launch(void* const* d_in, const int* in_sizes, int n_in,
                              void* d_out, int out_size)
{
    (void)in_sizes; (void)n_in; (void)out_size;
    const float* queries = (const float*)d_in[0];
    const float* keys    = (const float*)d_in[1];
    const float* pq      = (const float*)d_in[2];
    const float* pk      = (const float*)d_in[3];
    // d_in[4] = num_heads (fixed 8)
    const float* Wq = (const float*)d_in[5];
    const float* bq = (const float*)d_in[6];
    const float* Wk = (const float*)d_in[7];
    const float* bk = (const float*)d_in[8];
    const float* Wv = (const float*)d_in[9];
    const float* bv = (const float*)d_in[10];
    const float* Wo = (const float*)d_in[11];
    const float* bo = (const float*)d_in[12];
    const float* g0 = (const float*)d_in[13];
    const float* b0 = (const float*)d_in[14];
    const float* g1 = (const float*)d_in[15];
    const float* b1 = (const float*)d_in[16];
    float* out = (float*)d_out;

    float *q, *k, *v, *s, *t0, *t1;
    cudaGetSymbolAddress((void**)&q,  g_q);
    cudaGetSymbolAddress((void**)&k,  g_k);
    cudaGetSymbolAddress((void**)&v,  g_v);
    cudaGetSymbolAddress((void**)&s,  g_s);
    cudaGetSymbolAddress((void**)&t0, g_t0);
    cudaGetSymbolAddress((void**)&t1, g_t1);

    const float att_scale = 1.0f / sqrtf((float)DIM);

    // --- projections: q/k/v = X @ W + b   (8192x512 @ 512x512)
    {
        dim3 grid(DIM/128, MROWS/128, 1);
        gemm_nn_tc<EPI_BIAS><<<grid,256>>>(queries, Wq, q, MROWS, DIM, DIM, bq, 0);
        gemm_nn_tc<EPI_BIAS><<<grid,256>>>(keys,    Wk, k, MROWS, DIM, DIM, bk, 0);
        gemm_nn_tc<EPI_BIAS><<<grid,256>>>(keys,    Wv, v, MROWS, DIM, DIM, bv, 0);
    }

    // --- logits (masked, scaled)
    {
        dim3 grid(SEQK/128, SEQQ/128, BATCH*NH);
        logits_tc<<<grid,256>>>(q, k, s, pq, pk, att_scale);
    }

    // --- softmax rows
    softmax_k<<<BATCH*NH*SEQQ, 256>>>(s);

    // --- O = qh + A @ Vh
    {
        dim3 grid(1, SEQQ/128, BATCH*NH);
        av_tc<<<grid,256>>>(s, v, q, t0);
    }

    // --- LN0 (in place)
    ln_k<<<MROWS, 128>>>(t0, t0, g0, b0);

    // --- t1 = t0 + relu(t0 @ Wo + bo)
    {
        dim3 grid(DIM/128, MROWS/128, 1);
        gemm_nn_tc<EPI_RELU_RESID><<<grid,256>>>(t0, Wo, t1, MROWS, DIM, DIM, bo, t0);
    }

    // --- LN1 -> out
    ln_k<<<MROWS, 128>>>(t1, out, g1, b1);
}

// round 3
// speedup vs baseline: 3.4331x; 1.2945x over previous
#include <cuda_runtime.h>
#include <math.h>

// Problem constants
#define BATCH 8
#define NH    8
#define SEQQ  1024
#define SEQK  1024
#define DIM   512
#define HD    64
#define MROWS (BATCH*SEQQ)   // 8192

#define LN_EPS   1e-5f
#define MASK_INF 1e38f

#define EPI_BIAS       0
#define EPI_RELU_RESID 3

static __device__ float g_q [BATCH*SEQQ*DIM];
static __device__ float g_k [BATCH*SEQK*DIM];
static __device__ float g_v [BATCH*SEQK*DIM];
static __device__ float g_t0[BATCH*SEQQ*DIM];
static __device__ float g_t1[BATCH*SEQQ*DIM];

// ---------------------------------------------------------------------------
// tf32 helpers
// ---------------------------------------------------------------------------
__device__ __forceinline__ unsigned f2tf(float x) {
    unsigned u;
    asm("cvt.rna.tf32.f32 %0, %1;" : "=r"(u) : "f"(x));
    return u;
}

__device__ __forceinline__ void mma_tf32(float* c, const unsigned* a, const unsigned* b) {
    asm volatile(
        "mma.sync.aligned.m16n8k8.row.col.f32.tf32.tf32.f32 "
        "{%0,%1,%2,%3},{%4,%5,%6,%7},{%8,%9},{%0,%1,%2,%3};"
        : "+f"(c[0]), "+f"(c[1]), "+f"(c[2]), "+f"(c[3])
        : "r"(a[0]), "r"(a[1]), "r"(a[2]), "r"(a[3]), "r"(b[0]), "r"(b[1]));
}

// ---------------------------------------------------------------------------
// Dense NN GEMM: C[M,N] = A[M,K] @ B[K,N] + epilogue. BM=128,BN=128,BK=16.
// ---------------------------------------------------------------------------
template<int EPI>
__global__ __launch_bounds__(256)
void gemm_nn_tc(const float* __restrict__ A, const float* __restrict__ B,
                float* __restrict__ C, int M, int N, int K,
                const float* __restrict__ bias, const float* __restrict__ R)
{
    __shared__ unsigned As[128][20];   // [m][k], tf32 bits
    __shared__ unsigned Bs[16][136];   // [k][n], tf32 bits (8-word skew)

    const int tid  = threadIdx.x;
    const int m0   = blockIdx.y * 128;
    const int n0   = blockIdx.x * 128;
    const int lane = tid & 31;
    const int warp = tid >> 5;
    const int g    = lane >> 2;
    const int q    = lane & 3;
    const int mBase = (warp & 3) * 32;
    const int nBase = (warp >> 2) * 64;

    float acc[2][8][4];
    #pragma unroll
    for (int i = 0; i < 2; i++)
        #pragma unroll
        for (int j = 0; j < 8; j++)
            #pragma unroll
            for (int r = 0; r < 4; r++) acc[i][j][r] = 0.f;

    for (int k0 = 0; k0 < K; k0 += 16) {
        #pragma unroll
        for (int r = 0; r < 2; r++) {
            int f = tid + r * 256;            // 0..511
            int m = f >> 2, kq = (f & 3) << 2;
            float4 t = *(const float4*)(A + (size_t)(m0 + m) * K + k0 + kq);
            As[m][kq+0] = f2tf(t.x); As[m][kq+1] = f2tf(t.y);
            As[m][kq+2] = f2tf(t.z); As[m][kq+3] = f2tf(t.w);
        }
        #pragma unroll
        for (int r = 0; r < 2; r++) {
            int f = tid + r * 256;
            int kk = f >> 5, nc = (f & 31) << 2;
            float4 t = *(const float4*)(B + (size_t)(k0 + kk) * N + n0 + nc);
            Bs[kk][nc+0] = f2tf(t.x); Bs[kk][nc+1] = f2tf(t.y);
            Bs[kk][nc+2] = f2tf(t.z); Bs[kk][nc+3] = f2tf(t.w);
        }
        __syncthreads();

        #pragma unroll
        for (int ks = 0; ks < 16; ks += 8) {
            unsigned a[2][4], b[8][2];
            #pragma unroll
            for (int i = 0; i < 2; i++) {
                int row = mBase + i * 16 + g;
                a[i][0] = As[row    ][ks + q];
                a[i][1] = As[row + 8][ks + q];
                a[i][2] = As[row    ][ks + q + 4];
                a[i][3] = As[row + 8][ks + q + 4];
            }
            #pragma unroll
            for (int j = 0; j < 8; j++) {
                int col = nBase + j * 8 + g;
                b[j][0] = Bs[ks + q    ][col];
                b[j][1] = Bs[ks + q + 4][col];
            }
            #pragma unroll
            for (int i = 0; i < 2; i++)
                #pragma unroll
                for (int j = 0; j < 8; j++)
                    mma_tf32(acc[i][j], a[i], b[j]);
        }
        __syncthreads();
    }

    #pragma unroll
    for (int i = 0; i < 2; i++) {
        #pragma unroll
        for (int rr = 0; rr < 2; rr++) {
            int row = m0 + mBase + i * 16 + g + rr * 8;
            #pragma unroll
            for (int j = 0; j < 8; j++) {
                int col = n0 + nBase + j * 8 + 2 * q;
                float v0 = acc[i][j][rr*2 + 0];
                float v1 = acc[i][j][rr*2 + 1];
                if (EPI == EPI_BIAS) {
                    v0 += bias[col]; v1 += bias[col + 1];
                } else { // EPI_RELU_RESID
                    v0 = R[(size_t)row*N + col    ] + fmaxf(v0 + bias[col    ], 0.f);
                    v1 = R[(size_t)row*N + col + 1] + fmaxf(v1 + bias[col + 1], 0.f);
                }
                *(float2*)(C + (size_t)row * N + col) = make_float2(v0, v1);
            }
        }
    }
}

// ---------------------------------------------------------------------------
// Fused flash attention:  O = qh + softmax(mask(scale * Qh K^T)) @ Vh
// Grid: (SEQQ/128, BATCH*NH). Block: 256 threads = 8 warps.
// Each warp owns 16 query rows; streams K/V in 64-key tiles through smem.
// ---------------------------------------------------------------------------
__global__ __launch_bounds__(256)
void flash_tc(const float* __restrict__ Qm, const float* __restrict__ Km,
              const float* __restrict__ Vm,
              const float* __restrict__ pq, const float* __restrict__ pk,
              float* __restrict__ Om, float scale)
{
    __shared__ unsigned Ks[64][68];   // [key][k] tf32
    __shared__ unsigned Vs[64][68];   // [key][n] tf32
    __shared__ float    pks[64];

    const int bh = blockIdx.y;
    const int bz = bh >> 3, hz = bh & 7;
    const int m0 = blockIdx.x * 128;
    const int tid  = threadIdx.x;
    const int lane = tid & 31;
    const int w    = tid >> 5;
    const int g    = lane >> 2;
    const int q    = lane & 3;

    const size_t base = (size_t)bz * SEQQ * DIM + hz * HD;
    const float* Qp = Qm + base;
    const float* Kp = Km + base;
    const float* Vp = Vm + base;
    float*       Op = Om + base;

    const int row0 = m0 + w * 16 + g;
    const int row1 = row0 + 8;

    // Q fragments (held in registers for the whole kernel)
    unsigned qf[8][4];
    #pragma unroll
    for (int c = 0; c < 8; c++) {
        qf[c][0] = f2tf(Qp[(size_t)row0 * DIM + 8*c + q    ]);
        qf[c][1] = f2tf(Qp[(size_t)row1 * DIM + 8*c + q    ]);
        qf[c][2] = f2tf(Qp[(size_t)row0 * DIM + 8*c + q + 4]);
        qf[c][3] = f2tf(Qp[(size_t)row1 * DIM + 8*c + q + 4]);
    }

    const float pq0 = pq[bz * SEQQ + row0];
    const float pq1 = pq[bz * SEQQ + row1];

    float o[8][4];
    #pragma unroll
    for (int j = 0; j < 8; j++)
        #pragma unroll
        for (int r = 0; r < 4; r++) o[j][r] = 0.f;

    float rm0 = -INFINITY, rm1 = -INFINITY;
    float rl0 = 0.f, rl1 = 0.f;

    const int L0  = g * 4 + (q >> 1);
    const bool odd = (q & 1);

    for (int t = 0; t < 16; t++) {
        const int n0 = t * 64;

        // --- load K/V tiles (row-major 64x64 blocks) + pk slice
        #pragma unroll
        for (int r = 0; r < 4; r++) {
            int n  = (tid >> 4) + r * 16;
            int kc = (tid & 15) << 2;
            float4 kv = *(const float4*)(Kp + (size_t)(n0 + n) * DIM + kc);
            Ks[n][kc+0] = f2tf(kv.x); Ks[n][kc+1] = f2tf(kv.y);
            Ks[n][kc+2] = f2tf(kv.z); Ks[n][kc+3] = f2tf(kv.w);
            float4 vv = *(const float4*)(Vp + (size_t)(n0 + n) * DIM + kc);
            Vs[n][kc+0] = f2tf(vv.x); Vs[n][kc+1] = f2tf(vv.y);
            Vs[n][kc+2] = f2tf(vv.z); Vs[n][kc+3] = f2tf(vv.w);
        }
        if (tid < 64) pks[tid] = pk[bz * SEQK + n0 + tid];
        __syncthreads();

        // --- S = Q K^T  (16 x 64 per warp)
        float s[8][4];
        #pragma unroll
        for (int j = 0; j < 8; j++)
            #pragma unroll
            for (int r = 0; r < 4; r++) s[j][r] = 0.f;

        #pragma unroll
        for (int c = 0; c < 8; c++) {
            #pragma unroll
            for (int j = 0; j < 8; j++) {
                unsigned b[2];
                b[0] = Ks[8*j + g][8*c + q    ];
                b[1] = Ks[8*j + g][8*c + q + 4];
                mma_tf32(s[j], qf[c], b);
            }
        }

        // --- mask + online softmax (registers)
        float mt0 = -INFINITY, mt1 = -INFINITY;
        #pragma unroll
        for (int j = 0; j < 8; j++) {
            const float pka = pks[8*j + 2*q];
            const float pkb = pks[8*j + 2*q + 1];
            float x0 = pq0 * (s[j][0] * scale) - (1.f - pq0) * MASK_INF;
            float x1 = pq0 * (s[j][1] * scale) - (1.f - pq0) * MASK_INF;
            float x2 = pq1 * (s[j][2] * scale) - (1.f - pq1) * MASK_INF;
            float x3 = pq1 * (s[j][3] * scale) - (1.f - pq1) * MASK_INF;
            x0 = pka * x0 - (1.f - pka) * MASK_INF;
            x1 = pkb * x1 - (1.f - pkb) * MASK_INF;
            x2 = pka * x2 - (1.f - pka) * MASK_INF;
            x3 = pkb * x3 - (1.f - pkb) * MASK_INF;
            s[j][0] = x0; s[j][1] = x1; s[j][2] = x2; s[j][3] = x3;
            mt0 = fmaxf(mt0, fmaxf(x0, x1));
            mt1 = fmaxf(mt1, fmaxf(x2, x3));
        }
        mt0 = fmaxf(mt0, __shfl_xor_sync(0xffffffffu, mt0, 1));
        mt0 = fmaxf(mt0, __shfl_xor_sync(0xffffffffu, mt0, 2));
        mt1 = fmaxf(mt1, __shfl_xor_sync(0xffffffffu, mt1, 1));
        mt1 = fmaxf(mt1, __shfl_xor_sync(0xffffffffu, mt1, 2));

        const float mn0 = fmaxf(rm0, mt0);
        const float mn1 = fmaxf(rm1, mt1);
        const float sf0 = __expf(rm0 - mn0);
        const float sf1 = __expf(rm1 - mn1);
        rm0 = mn0; rm1 = mn1;

        float ps0 = 0.f, ps1 = 0.f;
        #pragma unroll
        for (int j = 0; j < 8; j++) {
            s[j][0] = __expf(s[j][0] - mn0); ps0 += s[j][0];
            s[j][1] = __expf(s[j][1] - mn0); ps0 += s[j][1];
            s[j][2] = __expf(s[j][2] - mn1); ps1 += s[j][2];
            s[j][3] = __expf(s[j][3] - mn1); ps1 += s[j][3];
        }
        ps0 += __shfl_xor_sync(0xffffffffu, ps0, 1);
        ps0 += __shfl_xor_sync(0xffffffffu, ps0, 2);
        ps1 += __shfl_xor_sync(0xffffffffu, ps1, 1);
        ps1 += __shfl_xor_sync(0xffffffffu, ps1, 2);
        rl0 = rl0 * sf0 + ps0;
        rl1 = rl1 * sf1 + ps1;

        #pragma unroll
        for (int j = 0; j < 8; j++) {
            o[j][0] *= sf0; o[j][1] *= sf0;
            o[j][2] *= sf1; o[j][3] *= sf1;
        }

        // --- O += P @ V  (C-layout -> A-fragment via shuffles)
        #pragma unroll
        for (int c = 0; c < 8; c++) {
            float v0 = __shfl_sync(0xffffffffu, s[c][0], L0);
            float v1 = __shfl_sync(0xffffffffu, s[c][1], L0);
            float v2 = __shfl_sync(0xffffffffu, s[c][2], L0);
            float v3 = __shfl_sync(0xffffffffu, s[c][3], L0);
            float w0 = __shfl_sync(0xffffffffu, s[c][0], L0 + 2);
            float w1 = __shfl_sync(0xffffffffu, s[c][1], L0 + 2);
            float w2 = __shfl_sync(0xffffffffu, s[c][2], L0 + 2);
            float w3 = __shfl_sync(0xffffffffu, s[c][3], L0 + 2);
            unsigned pf[4];
            pf[0] = f2tf(odd ? v1 : v0);
            pf[1] = f2tf(odd ? v3 : v2);
            pf[2] = f2tf(odd ? w1 : w0);
            pf[3] = f2tf(odd ? w3 : w2);
            #pragma unroll
            for (int j = 0; j < 8; j++) {
                unsigned b[2];
                b[0] = Vs[8*c + q    ][8*j + g];
                b[1] = Vs[8*c + q + 4][8*j + g];
                mma_tf32(o[j], pf, b);
            }
        }
        __syncthreads();
    }

    // --- epilogue: O/l + qh residual
    const float il0 = 1.f / rl0;
    const float il1 = 1.f / rl1;
    #pragma unroll
    for (int j = 0; j < 8; j++) {
        const int col = 8*j + 2*q;
        float2 r0 = *(const float2*)(Qp + (size_t)row0 * DIM + col);
        float2 r1 = *(const float2*)(Qp + (size_t)row1 * DIM + col);
        *(float2*)(Op + (size_t)row0 * DIM + col) =
            make_float2(o[j][0] * il0 + r0.x, o[j][1] * il0 + r0.y);
        *(float2*)(Op + (size_t)row1 * DIM + col) =
            make_float2(o[j][2] * il1 + r1.x, o[j][3] * il1 + r1.y);
    }
}

// ---------------------------------------------------------------------------
// LayerNorm over last dim (512). One block (128 threads) per row.
// ---------------------------------------------------------------------------
__global__ __launch_bounds__(128)
void ln_k(const float* __restrict__ X, float* __restrict__ Y,
          const float* __restrict__ gamma, const float* __restrict__ beta)
{
    const long row = blockIdx.x;
    const float* x = X + row*DIM;
    const int tid = threadIdx.x;
    const int w = tid >> 5, l = tid & 31;
    __shared__ float sred[4];

    float v[4];
    #pragma unroll
    for (int i = 0; i < 4; i++) v[i] = x[tid + i*128];

    float s = v[0]+v[1]+v[2]+v[3];
    #pragma unroll
    for (int o = 16; o > 0; o >>= 1) s += __shfl_xor_sync(0xffffffffu, s, o);
    if (l == 0) sred[w] = s;
    __syncthreads();
    float mu = (sred[0]+sred[1]+sred[2]+sred[3]) * (1.f/DIM);
    __syncthreads();

    float sq = 0.f;
    #pragma unroll
    for (int i = 0; i < 4; i++) { v[i] -= mu; sq += v[i]*v[i]; }
    #pragma unroll
    for (int o = 16; o > 0; o >>= 1) sq += __shfl_xor_sync(0xffffffffu, sq, o);
    if (l == 0) sred[w] = sq;
    __syncthreads();
    const float var = (sred[0]+sred[1]+sred[2]+sred[3]) * (1.f/DIM);
    const float r = rsqrtf(var + LN_EPS);

    #pragma unroll
    for (int i = 0; i < 4; i++) {
        const int c = tid + i*128;
        Y[row*DIM + c] = v[i]*r*gamma[c] + beta[c];
    }
}

// ---------------------------------------------------------------------------
extern "C" void kernel_launch(void* const* d_in, const int* in_sizes, int n_in,
                              void* d_out, int out_size)
{
    (void)in_sizes; (void)n_in; (void)out_size;
    const float* queries = (const float*)d_in[0];
    const float* keys    = (const float*)d_in[1];
    const float* pq      = (const float*)d_in[2];
    const float* pk      = (const float*)d_in[3];
    // d_in[4] = num_heads (fixed 8)
    const float* Wq = (const float*)d_in[5];
    const float* bq = (const float*)d_in[6];
    const float* Wk = (const float*)d_in[7];
    const float* bk = (const float*)d_in[8];
    const float* Wv = (const float*)d_in[9];
    const float* bv = (const float*)d_in[10];
    const float* Wo = (const float*)d_in[11];
    const float* bo = (const float*)d_in[12];
    const float* g0 = (const float*)d_in[13];
    const float* b0 = (const float*)d_in[14];
    const float* g1 = (const float*)d_in[15];
    const float* b1 = (const float*)d_in[16];
    float* out = (float*)d_out;

    float *q, *k, *v, *t0, *t1;
    cudaGetSymbolAddress((void**)&q,  g_q);
    cudaGetSymbolAddress((void**)&k,  g_k);
    cudaGetSymbolAddress((void**)&v,  g_v);
    cudaGetSymbolAddress((void**)&t0, g_t0);
    cudaGetSymbolAddress((void**)&t1, g_t1);

    const float att_scale = 1.0f / sqrtf((float)DIM);

    // --- projections: q/k/v = X @ W + b   (8192x512 @ 512x512)
    {
        dim3 grid(DIM/128, MROWS/128, 1);
        gemm_nn_tc<EPI_BIAS><<<grid,256>>>(queries, Wq, q, MROWS, DIM, DIM, bq, 0);
        gemm_nn_tc<EPI_BIAS><<<grid,256>>>(keys,    Wk, k, MROWS, DIM, DIM, bk, 0);
        gemm_nn_tc<EPI_BIAS><<<grid,256>>>(keys,    Wv, v, MROWS, DIM, DIM, bv, 0);
    }

    // --- fused attention: t0 = qh + softmax(mask(QK^T)) V
    {
        dim3 grid(SEQQ/128, BATCH*NH);
        flash_tc<<<grid,256>>>(q, k, v, pq, pk, t0, att_scale);
    }

    // --- LN0 (in place)
    ln_k<<<MROWS, 128>>>(t0, t0, g0, b0);

    // --- t1 = t0 + relu(t0 @ Wo + bo)
    {
        dim3 grid(DIM/128, MROWS/128, 1);
        gemm_nn_tc<EPI_RELU_RESID><<<grid,256>>>(t0, Wo, t1, MROWS, DIM, DIM, bo, t0);
    }

    // --- LN1 -> out
    ln_k<<<MROWS, 128>>>(t1, out, g1, b1);
}

// round 4
// speedup vs baseline: 3.7988x; 1.1065x over previous
#include <cuda_runtime.h>
#include <math.h>

// Problem constants
#define BATCH 8
#define NH    8
#define SEQQ  1024
#define SEQK  1024
#define DIM   512
#define HD    64
#define MROWS (BATCH*SEQQ)   // 8192

#define LN_EPS   1e-5f
#define MASK_INF 1e38f

#define EPI_BIAS       0
#define EPI_RELU_RESID 3

static __device__ float g_q [BATCH*SEQQ*DIM];
static __device__ float g_k [BATCH*SEQK*DIM];
static __device__ float g_v [BATCH*SEQK*DIM];
static __device__ float g_t0[BATCH*SEQQ*DIM];
static __device__ float g_t1[BATCH*SEQQ*DIM];

// ---------------------------------------------------------------------------
// tf32 helpers
// ---------------------------------------------------------------------------
__device__ __forceinline__ unsigned f2tf(float x) {
    unsigned u;
    asm("cvt.rna.tf32.f32 %0, %1;" : "=r"(u) : "f"(x));
    return u;
}

__device__ __forceinline__ void mma_tf32(float* c, const unsigned* a, const unsigned* b) {
    asm volatile(
        "mma.sync.aligned.m16n8k8.row.col.f32.tf32.tf32.f32 "
        "{%0,%1,%2,%3},{%4,%5,%6,%7},{%8,%9},{%0,%1,%2,%3};"
        : "+f"(c[0]), "+f"(c[1]), "+f"(c[2]), "+f"(c[3])
        : "r"(a[0]), "r"(a[1]), "r"(a[2]), "r"(a[3]), "r"(b[0]), "r"(b[1]));
}

// ---------------------------------------------------------------------------
// Dense NN GEMM: C[M,N] = A[M,K] @ B[K,N] + epilogue. BM=128,BN=128,BK=16.
// launch_bounds(256,2): cap regs at 128 so 2 CTAs fit per SM.
// ---------------------------------------------------------------------------
template<int EPI>
__global__ __launch_bounds__(256, 2)
void gemm_nn_tc(const float* __restrict__ A, const float* __restrict__ B,
                float* __restrict__ C, int M, int N, int K,
                const float* __restrict__ bias, const float* __restrict__ R)
{
    __shared__ unsigned As[128][20];   // [m][k], tf32 bits
    __shared__ unsigned Bs[16][136];   // [k][n], tf32 bits (8-word skew)

    const int tid  = threadIdx.x;
    const int m0   = blockIdx.y * 128;
    const int n0   = blockIdx.x * 128;
    const int lane = tid & 31;
    const int warp = tid >> 5;
    const int g    = lane >> 2;
    const int q    = lane & 3;
    const int mBase = (warp & 3) * 32;
    const int nBase = (warp >> 2) * 64;

    float acc[2][8][4];
    #pragma unroll
    for (int i = 0; i < 2; i++)
        #pragma unroll
        for (int j = 0; j < 8; j++)
            #pragma unroll
            for (int r = 0; r < 4; r++) acc[i][j][r] = 0.f;

    for (int k0 = 0; k0 < K; k0 += 16) {
        #pragma unroll
        for (int r = 0; r < 2; r++) {
            int f = tid + r * 256;            // 0..511
            int m = f >> 2, kq = (f & 3) << 2;
            float4 t = *(const float4*)(A + (size_t)(m0 + m) * K + k0 + kq);
            As[m][kq+0] = f2tf(t.x); As[m][kq+1] = f2tf(t.y);
            As[m][kq+2] = f2tf(t.z); As[m][kq+3] = f2tf(t.w);
        }
        #pragma unroll
        for (int r = 0; r < 2; r++) {
            int f = tid + r * 256;
            int kk = f >> 5, nc = (f & 31) << 2;
            float4 t = *(const float4*)(B + (size_t)(k0 + kk) * N + n0 + nc);
            Bs[kk][nc+0] = f2tf(t.x); Bs[kk][nc+1] = f2tf(t.y);
            Bs[kk][nc+2] = f2tf(t.z); Bs[kk][nc+3] = f2tf(t.w);
        }
        __syncthreads();

        #pragma unroll
        for (int ks = 0; ks < 16; ks += 8) {
            unsigned a[2][4], b[8][2];
            #pragma unroll
            for (int i = 0; i < 2; i++) {
                int row = mBase + i * 16 + g;
                a[i][0] = As[row    ][ks + q];
                a[i][1] = As[row + 8][ks + q];
                a[i][2] = As[row    ][ks + q + 4];
                a[i][3] = As[row + 8][ks + q + 4];
            }
            #pragma unroll
            for (int j = 0; j < 8; j++) {
                int col = nBase + j * 8 + g;
                b[j][0] = Bs[ks + q    ][col];
                b[j][1] = Bs[ks + q + 4][col];
            }
            #pragma unroll
            for (int i = 0; i < 2; i++)
                #pragma unroll
                for (int j = 0; j < 8; j++)
                    mma_tf32(acc[i][j], a[i], b[j]);
        }
        __syncthreads();
    }

    #pragma unroll
    for (int i = 0; i < 2; i++) {
        #pragma unroll
        for (int rr = 0; rr < 2; rr++) {
            int row = m0 + mBase + i * 16 + g + rr * 8;
            #pragma unroll
            for (int j = 0; j < 8; j++) {
                int col = n0 + nBase + j * 8 + 2 * q;
                float v0 = acc[i][j][rr*2 + 0];
                float v1 = acc[i][j][rr*2 + 1];
                if (EPI == EPI_BIAS) {
                    v0 += bias[col]; v1 += bias[col + 1];
                } else { // EPI_RELU_RESID
                    v0 = R[(size_t)row*N + col    ] + fmaxf(v0 + bias[col    ], 0.f);
                    v1 = R[(size_t)row*N + col + 1] + fmaxf(v1 + bias[col + 1], 0.f);
                }
                *(float2*)(C + (size_t)row * N + col) = make_float2(v0, v1);
            }
        }
    }
}

// ---------------------------------------------------------------------------
// Fused flash attention:  O = qh + softmax(mask(scale * Qh K^T)) @ Vh
// Grid: (SEQQ/128, BATCH*NH). Block: 256 threads = 8 warps.
// Q tile parked in shared (tf32) to keep regs <=128 -> 2 CTAs/SM.
// Dynamic smem: Qs[128][68] + Ks[64][68] + Vs[64][68] + pks[64] ~ 70 KB.
// ---------------------------------------------------------------------------
#define QS_STRIDE 68
#define FLASH_SMEM ((128*QS_STRIDE + 64*QS_STRIDE + 64*QS_STRIDE) * 4 + 64 * 4)

__global__ __launch_bounds__(256, 2)
void flash_tc(const float* __restrict__ Qm, const float* __restrict__ Km,
              const float* __restrict__ Vm,
              const float* __restrict__ pq, const float* __restrict__ pk,
              float* __restrict__ Om, float scale)
{
    extern __shared__ unsigned smem[];
    unsigned* Qs = smem;                       // [128][68]
    unsigned* Ks = Qs + 128 * QS_STRIDE;       // [64][68]
    unsigned* Vs = Ks + 64 * QS_STRIDE;        // [64][68]
    float*    pks = (float*)(Vs + 64 * QS_STRIDE);

    const int bh = blockIdx.y;
    const int bz = bh >> 3, hz = bh & 7;
    const int m0 = blockIdx.x * 128;
    const int tid  = threadIdx.x;
    const int lane = tid & 31;
    const int w    = tid >> 5;
    const int g    = lane >> 2;
    const int q    = lane & 3;

    const size_t base = (size_t)bz * SEQQ * DIM + hz * HD;
    const float* Qp = Qm + base;
    const float* Kp = Km + base;
    const float* Vp = Vm + base;
    float*       Op = Om + base;

    const int row0 = m0 + w * 16 + g;   // global q row (first half)
    const int lrow = w * 16 + g;        // local row in Qs

    // --- stage Q tile into shared as tf32 (once)
    #pragma unroll
    for (int r = 0; r < 8; r++) {
        int f = tid + r * 256;              // 0..2047 float4 groups
        int m = f >> 4, cq = (f & 15) << 2;
        float4 t = *(const float4*)(Qp + (size_t)(m0 + m) * DIM + cq);
        unsigned* dst = Qs + m * QS_STRIDE + cq;
        dst[0] = f2tf(t.x); dst[1] = f2tf(t.y);
        dst[2] = f2tf(t.z); dst[3] = f2tf(t.w);
    }

    const float pq0 = pq[bz * SEQQ + row0];
    const float pq1 = pq[bz * SEQQ + row0 + 8];

    float o[8][4];
    #pragma unroll
    for (int j = 0; j < 8; j++)
        #pragma unroll
        for (int r = 0; r < 4; r++) o[j][r] = 0.f;

    float rm0 = -INFINITY, rm1 = -INFINITY;
    float rl0 = 0.f, rl1 = 0.f;

    const int L0  = g * 4 + (q >> 1);
    const bool odd = (q & 1);

    __syncthreads();

    for (int t = 0; t < 16; t++) {
        const int n0 = t * 64;

        // --- load K/V tiles (64 keys x 64 dims) + pk slice
        #pragma unroll
        for (int r = 0; r < 4; r++) {
            int n  = (tid >> 4) + r * 16;
            int kc = (tid & 15) << 2;
            float4 kv = *(const float4*)(Kp + (size_t)(n0 + n) * DIM + kc);
            unsigned* kd = Ks + n * QS_STRIDE + kc;
            kd[0] = f2tf(kv.x); kd[1] = f2tf(kv.y);
            kd[2] = f2tf(kv.z); kd[3] = f2tf(kv.w);
            float4 vv = *(const float4*)(Vp + (size_t)(n0 + n) * DIM + kc);
            unsigned* vd = Vs + n * QS_STRIDE + kc;
            vd[0] = f2tf(vv.x); vd[1] = f2tf(vv.y);
            vd[2] = f2tf(vv.z); vd[3] = f2tf(vv.w);
        }
        if (tid < 64) pks[tid] = pk[bz * SEQK + n0 + tid];
        __syncthreads();

        // --- S = Q K^T  (16 x 64 per warp)
        float s[8][4];
        #pragma unroll
        for (int j = 0; j < 8; j++)
            #pragma unroll
            for (int r = 0; r < 4; r++) s[j][r] = 0.f;

        #pragma unroll
        for (int c = 0; c < 8; c++) {
            unsigned a[4];
            a[0] = Qs[(lrow    ) * QS_STRIDE + 8*c + q    ];
            a[1] = Qs[(lrow + 8) * QS_STRIDE + 8*c + q    ];
            a[2] = Qs[(lrow    ) * QS_STRIDE + 8*c + q + 4];
            a[3] = Qs[(lrow + 8) * QS_STRIDE + 8*c + q + 4];
            #pragma unroll
            for (int j = 0; j < 8; j++) {
                unsigned b[2];
                b[0] = Ks[(8*j + g) * QS_STRIDE + 8*c + q    ];
                b[1] = Ks[(8*j + g) * QS_STRIDE + 8*c + q + 4];
                mma_tf32(s[j], a, b);
            }
        }

        // --- mask + online softmax (registers)
        float mt0 = -INFINITY, mt1 = -INFINITY;
        #pragma unroll
        for (int j = 0; j < 8; j++) {
            const float pka = pks[8*j + 2*q];
            const float pkb = pks[8*j + 2*q + 1];
            float x0 = pq0 * (s[j][0] * scale) - (1.f - pq0) * MASK_INF;
            float x1 = pq0 * (s[j][1] * scale) - (1.f - pq0) * MASK_INF;
            float x2 = pq1 * (s[j][2] * scale) - (1.f - pq1) * MASK_INF;
            float x3 = pq1 * (s[j][3] * scale) - (1.f - pq1) * MASK_INF;
            x0 = pka * x0 - (1.f - pka) * MASK_INF;
            x1 = pkb * x1 - (1.f - pkb) * MASK_INF;
            x2 = pka * x2 - (1.f - pka) * MASK_INF;
            x3 = pkb * x3 - (1.f - pkb) * MASK_INF;
            s[j][0] = x0; s[j][1] = x1; s[j][2] = x2; s[j][3] = x3;
            mt0 = fmaxf(mt0, fmaxf(x0, x1));
            mt1 = fmaxf(mt1, fmaxf(x2, x3));
        }
        mt0 = fmaxf(mt0, __shfl_xor_sync(0xffffffffu, mt0, 1));
        mt0 = fmaxf(mt0, __shfl_xor_sync(0xffffffffu, mt0, 2));
        mt1 = fmaxf(mt1, __shfl_xor_sync(0xffffffffu, mt1, 1));
        mt1 = fmaxf(mt1, __shfl_xor_sync(0xffffffffu, mt1, 2));

        const float mn0 = fmaxf(rm0, mt0);
        const float mn1 = fmaxf(rm1, mt1);
        const float sf0 = __expf(rm0 - mn0);
        const float sf1 = __expf(rm1 - mn1);
        rm0 = mn0; rm1 = mn1;

        float ps0 = 0.f, ps1 = 0.f;
        #pragma unroll
        for (int j = 0; j < 8; j++) {
            s[j][0] = __expf(s[j][0] - mn0); ps0 += s[j][0];
            s[j][1] = __expf(s[j][1] - mn0); ps0 += s[j][1];
            s[j][2] = __expf(s[j][2] - mn1); ps1 += s[j][2];
            s[j][3] = __expf(s[j][3] - mn1); ps1 += s[j][3];
        }
        ps0 += __shfl_xor_sync(0xffffffffu, ps0, 1);
        ps0 += __shfl_xor_sync(0xffffffffu, ps0, 2);
        ps1 += __shfl_xor_sync(0xffffffffu, ps1, 1);
        ps1 += __shfl_xor_sync(0xffffffffu, ps1, 2);
        rl0 = rl0 * sf0 + ps0;
        rl1 = rl1 * sf1 + ps1;

        #pragma unroll
        for (int j = 0; j < 8; j++) {
            o[j][0] *= sf0; o[j][1] *= sf0;
            o[j][2] *= sf1; o[j][3] *= sf1;
        }

        // --- O += P @ V  (C-layout -> A-fragment via shuffles)
        #pragma unroll
        for (int c = 0; c < 8; c++) {
            float v0 = __shfl_sync(0xffffffffu, s[c][0], L0);
            float v1 = __shfl_sync(0xffffffffu, s[c][1], L0);
            float v2 = __shfl_sync(0xffffffffu, s[c][2], L0);
            float v3 = __shfl_sync(0xffffffffu, s[c][3], L0);
            float w0 = __shfl_sync(0xffffffffu, s[c][0], L0 + 2);
            float w1 = __shfl_sync(0xffffffffu, s[c][1], L0 + 2);
            float w2 = __shfl_sync(0xffffffffu, s[c][2], L0 + 2);
            float w3 = __shfl_sync(0xffffffffu, s[c][3], L0 + 2);
            unsigned pf[4];
            pf[0] = f2tf(odd ? v1 : v0);
            pf[1] = f2tf(odd ? v3 : v2);
            pf[2] = f2tf(odd ? w1 : w0);
            pf[3] = f2tf(odd ? w3 : w2);
            #pragma unroll
            for (int j = 0; j < 8; j++) {
                unsigned b[2];
                b[0] = Vs[(8*c + q    ) * QS_STRIDE + 8*j + g];
                b[1] = Vs[(8*c + q + 4) * QS_STRIDE + 8*j + g];
                mma_tf32(o[j], pf, b);
            }
        }
        __syncthreads();
    }

    // --- epilogue: O/l + qh residual
    const float il0 = 1.f / rl0;
    const float il1 = 1.f / rl1;
    #pragma unroll
    for (int j = 0; j < 8; j++) {
        const int col = 8*j + 2*q;
        float2 r0 = *(const float2*)(Qp + (size_t)row0 * DIM + col);
        float2 r1 = *(const float2*)(Qp + (size_t)(row0 + 8) * DIM + col);
        *(float2*)(Op + (size_t)row0 * DIM + col) =
            make_float2(o[j][0] * il0 + r0.x, o[j][1] * il0 + r0.y);
        *(float2*)(Op + (size_t)(row0 + 8) * DIM + col) =
            make_float2(o[j][2] * il1 + r1.x, o[j][3] * il1 + r1.y);
    }
}

// ---------------------------------------------------------------------------
// LayerNorm over last dim (512). One block (128 threads) per row.
// ---------------------------------------------------------------------------
__global__ __launch_bounds__(128)
void ln_k(const float* __restrict__ X, float* __restrict__ Y,
          const float* __restrict__ gamma, const float* __restrict__ beta)
{
    const long row = blockIdx.x;
    const float* x = X + row*DIM;
    const int tid = threadIdx.x;
    const int w = tid >> 5, l = tid & 31;
    __shared__ float sred[4];

    float v[4];
    #pragma unroll
    for (int i = 0; i < 4; i++) v[i] = x[tid + i*128];

    float s = v[0]+v[1]+v[2]+v[3];
    #pragma unroll
    for (int o = 16; o > 0; o >>= 1) s += __shfl_xor_sync(0xffffffffu, s, o);
    if (l == 0) sred[w] = s;
    __syncthreads();
    float mu = (sred[0]+sred[1]+sred[2]+sred[3]) * (1.f/DIM);
    __syncthreads();

    float sq = 0.f;
    #pragma unroll
    for (int i = 0; i < 4; i++) { v[i] -= mu; sq += v[i]*v[i]; }
    #pragma unroll
    for (int o = 16; o > 0; o >>= 1) sq += __shfl_xor_sync(0xffffffffu, sq, o);
    if (l == 0) sred[w] = sq;
    __syncthreads();
    const float var = (sred[0]+sred[1]+sred[2]+sred[3]) * (1.f/DIM);
    const float r = rsqrtf(var + LN_EPS);

    #pragma unroll
    for (int i = 0; i < 4; i++) {
        const int c = tid + i*128;
        Y[row*DIM + c] = v[i]*r*gamma[c] + beta[c];
    }
}

// ---------------------------------------------------------------------------
extern "C" void kernel_launch(void* const* d_in, const int* in_sizes, int n_in,
                              void* d_out, int out_size)
{
    (void)in_sizes; (void)n_in; (void)out_size;
    const float* queries = (const float*)d_in[0];
    const float* keys    = (const float*)d_in[1];
    const float* pq      = (const float*)d_in[2];
    const float* pk      = (const float*)d_in[3];
    // d_in[4] = num_heads (fixed 8)
    const float* Wq = (const float*)d_in[5];
    const float* bq = (const float*)d_in[6];
    const float* Wk = (const float*)d_in[7];
    const float* bk = (const float*)d_in[8];
    const float* Wv = (const float*)d_in[9];
    const float* bv = (const float*)d_in[10];
    const float* Wo = (const float*)d_in[11];
    const float* bo = (const float*)d_in[12];
    const float* g0 = (const float*)d_in[13];
    const float* b0 = (const float*)d_in[14];
    const float* g1 = (const float*)d_in[15];
    const float* b1 = (const float*)d_in[16];
    float* out = (float*)d_out;

    float *q, *k, *v, *t0, *t1;
    cudaGetSymbolAddress((void**)&q,  g_q);
    cudaGetSymbolAddress((void**)&k,  g_k);
    cudaGetSymbolAddress((void**)&v,  g_v);
    cudaGetSymbolAddress((void**)&t0, g_t0);
    cudaGetSymbolAddress((void**)&t1, g_t1);

    const float att_scale = 1.0f / sqrtf((float)DIM);

    // --- projections: q/k/v = X @ W + b   (8192x512 @ 512x512)
    {
        dim3 grid(DIM/128, MROWS/128, 1);
        gemm_nn_tc<EPI_BIAS><<<grid,256>>>(queries, Wq, q, MROWS, DIM, DIM, bq, 0);
        gemm_nn_tc<EPI_BIAS><<<grid,256>>>(keys,    Wk, k, MROWS, DIM, DIM, bk, 0);
        gemm_nn_tc<EPI_BIAS><<<grid,256>>>(keys,    Wv, v, MROWS, DIM, DIM, bv, 0);
    }

    // --- fused attention: t0 = qh + softmax(mask(QK^T)) V
    {
        cudaFuncSetAttribute(flash_tc, cudaFuncAttributeMaxDynamicSharedMemorySize,
                             FLASH_SMEM);
        dim3 grid(SEQQ/128, BATCH*NH);
        flash_tc<<<grid,256,FLASH_SMEM>>>(q, k, v, pq, pk, t0, att_scale);
    }

    // --- LN0 (in place)
    ln_k<<<MROWS, 128>>>(t0, t0, g0, b0);

    // --- t1 = t0 + relu(t0 @ Wo + bo)
    {
        dim3 grid(DIM/128, MROWS/128, 1);
        gemm_nn_tc<EPI_RELU_RESID><<<grid,256>>>(t0, Wo, t1, MROWS, DIM, DIM, bo, t0);
    }

    // --- LN1 -> out
    ln_k<<<MROWS, 128>>>(t1, out, g1, b1);
}

// round 5
// speedup vs baseline: 4.2657x; 1.1229x over previous
#include <cuda_runtime.h>
#include <math.h>

// Problem constants
#define BATCH 8
#define NH    8
#define SEQQ  1024
#define SEQK  1024
#define DIM   512
#define HD    64
#define MROWS (BATCH*SEQQ)   // 8192

#define LN_EPS   1e-5f
#define MASK_INF 1e38f

#define EPI_BIAS       0
#define EPI_RELU_RESID 3

static __device__ float g_q [BATCH*SEQQ*DIM];
static __device__ float g_k [BATCH*SEQK*DIM];
static __device__ float g_v [BATCH*SEQK*DIM];
static __device__ float g_t0[BATCH*SEQQ*DIM];
static __device__ float g_t1[BATCH*SEQQ*DIM];

// ---------------------------------------------------------------------------
// tf32 helpers
// ---------------------------------------------------------------------------
__device__ __forceinline__ unsigned f2tf(float x) {
    unsigned u;
    asm("cvt.rna.tf32.f32 %0, %1;" : "=r"(u) : "f"(x));
    return u;
}

__device__ __forceinline__ void mma_tf32(float* c, const unsigned* a, const unsigned* b) {
    asm volatile(
        "mma.sync.aligned.m16n8k8.row.col.f32.tf32.tf32.f32 "
        "{%0,%1,%2,%3},{%4,%5,%6,%7},{%8,%9},{%0,%1,%2,%3};"
        : "+f"(c[0]), "+f"(c[1]), "+f"(c[2]), "+f"(c[3])
        : "r"(a[0]), "r"(a[1]), "r"(a[2]), "r"(a[3]), "r"(b[0]), "r"(b[1]));
}

// ---------------------------------------------------------------------------
// Dense NN GEMM: C[M,N] = A[M,K] @ B[K,N] + epilogue. BM=128,BN=128,BK=16.
// Double-buffered smem (2 stages) + register staging: LDG for k+1 overlaps
// the mma block for k. One __syncthreads per k-iter.
// ---------------------------------------------------------------------------
template<int EPI>
__global__ __launch_bounds__(256, 2)
void gemm_nn_tc(const float* __restrict__ A, const float* __restrict__ B,
                float* __restrict__ C, int M, int N, int K,
                const float* __restrict__ bias, const float* __restrict__ R)
{
    __shared__ unsigned As[2][128][20];   // [stage][m][k], tf32 bits
    __shared__ unsigned Bs[2][16][136];   // [stage][k][n], tf32 bits (8-word skew)

    const int tid  = threadIdx.x;
    const int m0   = blockIdx.y * 128;
    const int n0   = blockIdx.x * 128;
    const int lane = tid & 31;
    const int warp = tid >> 5;
    const int g    = lane >> 2;
    const int q    = lane & 3;
    const int mBase = (warp & 3) * 32;
    const int nBase = (warp >> 2) * 64;

    // per-thread staging coordinates (2 chunks of 256 threads each)
    const int am[2] = { (tid      ) >> 2, (tid + 256) >> 2 };
    const int ak[2] = { ((tid      ) & 3) << 2, ((tid + 256) & 3) << 2 };
    const int bk[2] = { (tid      ) >> 5, (tid + 256) >> 5 };
    const int bn[2] = { ((tid      ) & 31) << 2, ((tid + 256) & 31) << 2 };

    float acc[2][8][4];
    #pragma unroll
    for (int i = 0; i < 2; i++)
        #pragma unroll
        for (int j = 0; j < 8; j++)
            #pragma unroll
            for (int r = 0; r < 4; r++) acc[i][j][r] = 0.f;

    float4 ra[2], rb[2];

    // --- prologue: load k-block 0 into stage 0
    #pragma unroll
    for (int r = 0; r < 2; r++) {
        ra[r] = *(const float4*)(A + (size_t)(m0 + am[r]) * K + ak[r]);
        rb[r] = *(const float4*)(B + (size_t)bk[r] * N + n0 + bn[r]);
    }
    #pragma unroll
    for (int r = 0; r < 2; r++) {
        As[0][am[r]][ak[r]+0] = f2tf(ra[r].x); As[0][am[r]][ak[r]+1] = f2tf(ra[r].y);
        As[0][am[r]][ak[r]+2] = f2tf(ra[r].z); As[0][am[r]][ak[r]+3] = f2tf(ra[r].w);
        Bs[0][bk[r]][bn[r]+0] = f2tf(rb[r].x); Bs[0][bk[r]][bn[r]+1] = f2tf(rb[r].y);
        Bs[0][bk[r]][bn[r]+2] = f2tf(rb[r].z); Bs[0][bk[r]][bn[r]+3] = f2tf(rb[r].w);
    }
    __syncthreads();

    int st = 0;
    for (int k0 = 16; k0 < K; k0 += 16) {
        // --- issue loads for next k-block (latency hidden behind mma below)
        #pragma unroll
        for (int r = 0; r < 2; r++) {
            ra[r] = *(const float4*)(A + (size_t)(m0 + am[r]) * K + k0 + ak[r]);
            rb[r] = *(const float4*)(B + (size_t)(k0 + bk[r]) * N + n0 + bn[r]);
        }

        // --- compute current stage
        #pragma unroll
        for (int ks = 0; ks < 16; ks += 8) {
            unsigned a[2][4], b[8][2];
            #pragma unroll
            for (int i = 0; i < 2; i++) {
                int row = mBase + i * 16 + g;
                a[i][0] = As[st][row    ][ks + q];
                a[i][1] = As[st][row + 8][ks + q];
                a[i][2] = As[st][row    ][ks + q + 4];
                a[i][3] = As[st][row + 8][ks + q + 4];
            }
            #pragma unroll
            for (int j = 0; j < 8; j++) {
                int col = nBase + j * 8 + g;
                b[j][0] = Bs[st][ks + q    ][col];
                b[j][1] = Bs[st][ks + q + 4][col];
            }
            #pragma unroll
            for (int i = 0; i < 2; i++)
                #pragma unroll
                for (int j = 0; j < 8; j++)
                    mma_tf32(acc[i][j], a[i], b[j]);
        }

        // --- store staged data into the other stage
        const int ns = st ^ 1;
        #pragma unroll
        for (int r = 0; r < 2; r++) {
            As[ns][am[r]][ak[r]+0] = f2tf(ra[r].x); As[ns][am[r]][ak[r]+1] = f2tf(ra[r].y);
            As[ns][am[r]][ak[r]+2] = f2tf(ra[r].z); As[ns][am[r]][ak[r]+3] = f2tf(ra[r].w);
            Bs[ns][bk[r]][bn[r]+0] = f2tf(rb[r].x); Bs[ns][bk[r]][bn[r]+1] = f2tf(rb[r].y);
            Bs[ns][bk[r]][bn[r]+2] = f2tf(rb[r].z); Bs[ns][bk[r]][bn[r]+3] = f2tf(rb[r].w);
        }
        __syncthreads();
        st = ns;
    }

    // --- final k-block
    #pragma unroll
    for (int ks = 0; ks < 16; ks += 8) {
        unsigned a[2][4], b[8][2];
        #pragma unroll
        for (int i = 0; i < 2; i++) {
            int row = mBase + i * 16 + g;
            a[i][0] = As[st][row    ][ks + q];
            a[i][1] = As[st][row + 8][ks + q];
            a[i][2] = As[st][row    ][ks + q + 4];
            a[i][3] = As[st][row + 8][ks + q + 4];
        }
        #pragma unroll
        for (int j = 0; j < 8; j++) {
            int col = nBase + j * 8 + g;
            b[j][0] = Bs[st][ks + q    ][col];
            b[j][1] = Bs[st][ks + q + 4][col];
        }
        #pragma unroll
        for (int i = 0; i < 2; i++)
            #pragma unroll
            for (int j = 0; j < 8; j++)
                mma_tf32(acc[i][j], a[i], b[j]);
    }

    // --- epilogue
    #pragma unroll
    for (int i = 0; i < 2; i++) {
        #pragma unroll
        for (int rr = 0; rr < 2; rr++) {
            int row = m0 + mBase + i * 16 + g + rr * 8;
            #pragma unroll
            for (int j = 0; j < 8; j++) {
                int col = n0 + nBase + j * 8 + 2 * q;
                float v0 = acc[i][j][rr*2 + 0];
                float v1 = acc[i][j][rr*2 + 1];
                if (EPI == EPI_BIAS) {
                    v0 += bias[col]; v1 += bias[col + 1];
                } else { // EPI_RELU_RESID
                    v0 = R[(size_t)row*N + col    ] + fmaxf(v0 + bias[col    ], 0.f);
                    v1 = R[(size_t)row*N + col + 1] + fmaxf(v1 + bias[col + 1], 0.f);
                }
                *(float2*)(C + (size_t)row * N + col) = make_float2(v0, v1);
            }
        }
    }
}

// ---------------------------------------------------------------------------
// Fused flash attention:  O = qh + softmax(mask(scale * Qh K^T)) @ Vh
// Grid: (SEQQ/128, BATCH*NH). Block: 256 threads = 8 warps.
// Q parked in shared (tf32). Vs stride 72 -> conflict-free b-fragment loads
// (bank index 8q+g); Ks/Qs stride 68 (bank index 4g+q) already conflict-free.
// ---------------------------------------------------------------------------
#define KS_STRIDE 68
#define VS_STRIDE 72
#define FLASH_SMEM ((128*KS_STRIDE + 64*KS_STRIDE + 64*VS_STRIDE) * 4 + 64 * 4)

__global__ __launch_bounds__(256, 2)
void flash_tc(const float* __restrict__ Qm, const float* __restrict__ Km,
              const float* __restrict__ Vm,
              const float* __restrict__ pq, const float* __restrict__ pk,
              float* __restrict__ Om, float scale)
{
    extern __shared__ unsigned smem[];
    unsigned* Qs = smem;                       // [128][68]
    unsigned* Ks = Qs + 128 * KS_STRIDE;       // [64][68]
    unsigned* Vs = Ks + 64 * KS_STRIDE;        // [64][72]
    float*    pks = (float*)(Vs + 64 * VS_STRIDE);

    const int bh = blockIdx.y;
    const int bz = bh >> 3, hz = bh & 7;
    const int m0 = blockIdx.x * 128;
    const int tid  = threadIdx.x;
    const int lane = tid & 31;
    const int w    = tid >> 5;
    const int g    = lane >> 2;
    const int q    = lane & 3;

    const size_t base = (size_t)bz * SEQQ * DIM + hz * HD;
    const float* Qp = Qm + base;
    const float* Kp = Km + base;
    const float* Vp = Vm + base;
    float*       Op = Om + base;

    const int row0 = m0 + w * 16 + g;   // global q row (first half)
    const int lrow = w * 16 + g;        // local row in Qs

    // --- stage Q tile into shared as tf32 (once)
    #pragma unroll
    for (int r = 0; r < 8; r++) {
        int f = tid + r * 256;              // 0..2047 float4 groups
        int m = f >> 4, cq = (f & 15) << 2;
        float4 t = *(const float4*)(Qp + (size_t)(m0 + m) * DIM + cq);
        unsigned* dst = Qs + m * KS_STRIDE + cq;
        dst[0] = f2tf(t.x); dst[1] = f2tf(t.y);
        dst[2] = f2tf(t.z); dst[3] = f2tf(t.w);
    }

    const float pq0 = pq[bz * SEQQ + row0];
    const float pq1 = pq[bz * SEQQ + row0 + 8];

    float o[8][4];
    #pragma unroll
    for (int j = 0; j < 8; j++)
        #pragma unroll
        for (int r = 0; r < 4; r++) o[j][r] = 0.f;

    float rm0 = -INFINITY, rm1 = -INFINITY;
    float rl0 = 0.f, rl1 = 0.f;

    const int L0  = g * 4 + (q >> 1);
    const bool odd = (q & 1);

    __syncthreads();

    for (int t = 0; t < 16; t++) {
        const int n0 = t * 64;

        // --- load K/V tiles (64 keys x 64 dims) + pk slice
        #pragma unroll
        for (int r = 0; r < 4; r++) {
            int n  = (tid >> 4) + r * 16;
            int kc = (tid & 15) << 2;
            float4 kv = *(const float4*)(Kp + (size_t)(n0 + n) * DIM + kc);
            unsigned* kd = Ks + n * KS_STRIDE + kc;
            kd[0] = f2tf(kv.x); kd[1] = f2tf(kv.y);
            kd[2] = f2tf(kv.z); kd[3] = f2tf(kv.w);
            float4 vv = *(const float4*)(Vp + (size_t)(n0 + n) * DIM + kc);
            unsigned* vd = Vs + n * VS_STRIDE + kc;
            vd[0] = f2tf(vv.x); vd[1] = f2tf(vv.y);
            vd[2] = f2tf(vv.z); vd[3] = f2tf(vv.w);
        }
        if (tid < 64) pks[tid] = pk[bz * SEQK + n0 + tid];
        __syncthreads();

        // --- S = Q K^T  (16 x 64 per warp)
        float s[8][4];
        #pragma unroll
        for (int j = 0; j < 8; j++)
            #pragma unroll
            for (int r = 0; r < 4; r++) s[j][r] = 0.f;

        #pragma unroll
        for (int c = 0; c < 8; c++) {
            unsigned a[4];
            a[0] = Qs[(lrow    ) * KS_STRIDE + 8*c + q    ];
            a[1] = Qs[(lrow + 8) * KS_STRIDE + 8*c + q    ];
            a[2] = Qs[(lrow    ) * KS_STRIDE + 8*c + q + 4];
            a[3] = Qs[(lrow + 8) * KS_STRIDE + 8*c + q + 4];
            #pragma unroll
            for (int j = 0; j < 8; j++) {
                unsigned b[2];
                b[0] = Ks[(8*j + g) * KS_STRIDE + 8*c + q    ];
                b[1] = Ks[(8*j + g) * KS_STRIDE + 8*c + q + 4];
                mma_tf32(s[j], a, b);
            }
        }

        // --- mask + online softmax (registers)
        float mt0 = -INFINITY, mt1 = -INFINITY;
        #pragma unroll
        for (int j = 0; j < 8; j++) {
            const float pka = pks[8*j + 2*q];
            const float pkb = pks[8*j + 2*q + 1];
            float x0 = pq0 * (s[j][0] * scale) - (1.f - pq0) * MASK_INF;
            float x1 = pq0 * (s[j][1] * scale) - (1.f - pq0) * MASK_INF;
            float x2 = pq1 * (s[j][2] * scale) - (1.f - pq1) * MASK_INF;
            float x3 = pq1 * (s[j][3] * scale) - (1.f - pq1) * MASK_INF;
            x0 = pka * x0 - (1.f - pka) * MASK_INF;
            x1 = pkb * x1 - (1.f - pkb) * MASK_INF;
            x2 = pka * x2 - (1.f - pka) * MASK_INF;
            x3 = pkb * x3 - (1.f - pkb) * MASK_INF;
            s[j][0] = x0; s[j][1] = x1; s[j][2] = x2; s[j][3] = x3;
            mt0 = fmaxf(mt0, fmaxf(x0, x1));
            mt1 = fmaxf(mt1, fmaxf(x2, x3));
        }
        mt0 = fmaxf(mt0, __shfl_xor_sync(0xffffffffu, mt0, 1));
        mt0 = fmaxf(mt0, __shfl_xor_sync(0xffffffffu, mt0, 2));
        mt1 = fmaxf(mt1, __shfl_xor_sync(0xffffffffu, mt1, 1));
        mt1 = fmaxf(mt1, __shfl_xor_sync(0xffffffffu, mt1, 2));

        const float mn0 = fmaxf(rm0, mt0);
        const float mn1 = fmaxf(rm1, mt1);
        const float sf0 = __expf(rm0 - mn0);
        const float sf1 = __expf(rm1 - mn1);
        rm0 = mn0; rm1 = mn1;

        float ps0 = 0.f, ps1 = 0.f;
        #pragma unroll
        for (int j = 0; j < 8; j++) {
            s[j][0] = __expf(s[j][0] - mn0); ps0 += s[j][0];
            s[j][1] = __expf(s[j][1] - mn0); ps0 += s[j][1];
            s[j][2] = __expf(s[j][2] - mn1); ps1 += s[j][2];
            s[j][3] = __expf(s[j][3] - mn1); ps1 += s[j][3];
        }
        ps0 += __shfl_xor_sync(0xffffffffu, ps0, 1);
        ps0 += __shfl_xor_sync(0xffffffffu, ps0, 2);
        ps1 += __shfl_xor_sync(0xffffffffu, ps1, 1);
        ps1 += __shfl_xor_sync(0xffffffffu, ps1, 2);
        rl0 = rl0 * sf0 + ps0;
        rl1 = rl1 * sf1 + ps1;

        #pragma unroll
        for (int j = 0; j < 8; j++) {
            o[j][0] *= sf0; o[j][1] *= sf0;
            o[j][2] *= sf1; o[j][3] *= sf1;
        }

        // --- O += P @ V  (C-layout -> A-fragment via shuffles)
        #pragma unroll
        for (int c = 0; c < 8; c++) {
            float v0 = __shfl_sync(0xffffffffu, s[c][0], L0);
            float v1 = __shfl_sync(0xffffffffu, s[c][1], L0);
            float v2 = __shfl_sync(0xffffffffu, s[c][2], L0);
            float v3 = __shfl_sync(0xffffffffu, s[c][3], L0);
            float w0 = __shfl_sync(0xffffffffu, s[c][0], L0 + 2);
            float w1 = __shfl_sync(0xffffffffu, s[c][1], L0 + 2);
            float w2 = __shfl_sync(0xffffffffu, s[c][2], L0 + 2);
            float w3 = __shfl_sync(0xffffffffu, s[c][3], L0 + 2);
            unsigned pf[4];
            pf[0] = f2tf(odd ? v1 : v0);
            pf[1] = f2tf(odd ? v3 : v2);
            pf[2] = f2tf(odd ? w1 : w0);
            pf[3] = f2tf(odd ? w3 : w2);
            #pragma unroll
            for (int j = 0; j < 8; j++) {
                unsigned b[2];
                b[0] = Vs[(8*c + q    ) * VS_STRIDE + 8*j + g];
                b[1] = Vs[(8*c + q + 4) * VS_STRIDE + 8*j + g];
                mma_tf32(o[j], pf, b);
            }
        }
        __syncthreads();
    }

    // --- epilogue: O/l + qh residual
    const float il0 = 1.f / rl0;
    const float il1 = 1.f / rl1;
    #pragma unroll
    for (int j = 0; j < 8; j++) {
        const int col = 8*j + 2*q;
        float2 r0 = *(const float2*)(Qp + (size_t)row0 * DIM + col);
        float2 r1 = *(const float2*)(Qp + (size_t)(row0 + 8) * DIM + col);
        *(float2*)(Op + (size_t)row0 * DIM + col) =
            make_float2(o[j][0] * il0 + r0.x, o[j][1] * il0 + r0.y);
        *(float2*)(Op + (size_t)(row0 + 8) * DIM + col) =
            make_float2(o[j][2] * il1 + r1.x, o[j][3] * il1 + r1.y);
    }
}

// ---------------------------------------------------------------------------
// LayerNorm over last dim (512). One block (128 threads) per row.
// ---------------------------------------------------------------------------
__global__ __launch_bounds__(128)
void ln_k(const float* __restrict__ X, float* __restrict__ Y,
          const float* __restrict__ gamma, const float* __restrict__ beta)
{
    const long row = blockIdx.x;
    const float* x = X + row*DIM;
    const int tid = threadIdx.x;
    const int w = tid >> 5, l = tid & 31;
    __shared__ float sred[4];

    float v[4];
    #pragma unroll
    for (int i = 0; i < 4; i++) v[i] = x[tid + i*128];

    float s = v[0]+v[1]+v[2]+v[3];
    #pragma unroll
    for (int o = 16; o > 0; o >>= 1) s += __shfl_xor_sync(0xffffffffu, s, o);
    if (l == 0) sred[w] = s;
    __syncthreads();
    float mu = (sred[0]+sred[1]+sred[2]+sred[3]) * (1.f/DIM);
    __syncthreads();

    float sq = 0.f;
    #pragma unroll
    for (int i = 0; i < 4; i++) { v[i] -= mu; sq += v[i]*v[i]; }
    #pragma unroll
    for (int o = 16; o > 0; o >>= 1) sq += __shfl_xor_sync(0xffffffffu, sq, o);
    if (l == 0) sred[w] = sq;
    __syncthreads();
    const float var = (sred[0]+sred[1]+sred[2]+sred[3]) * (1.f/DIM);
    const float r = rsqrtf(var + LN_EPS);

    #pragma unroll
    for (int i = 0; i < 4; i++) {
        const int c = tid + i*128;
        Y[row*DIM + c] = v[i]*r*gamma[c] + beta[c];
    }
}

// ---------------------------------------------------------------------------
extern "C" void kernel_launch(void* const* d_in, const int* in_sizes, int n_in,
                              void* d_out, int out_size)
{
    (void)in_sizes; (void)n_in; (void)out_size;
    const float* queries = (const float*)d_in[0];
    const float* keys    = (const float*)d_in[1];
    const float* pq      = (const float*)d_in[2];
    const float* pk      = (const float*)d_in[3];
    // d_in[4] = num_heads (fixed 8)
    const float* Wq = (const float*)d_in[5];
    const float* bq = (const float*)d_in[6];
    const float* Wk = (const float*)d_in[7];
    const float* bk = (const float*)d_in[8];
    const float* Wv = (const float*)d_in[9];
    const float* bv = (const float*)d_in[10];
    const float* Wo = (const float*)d_in[11];
    const float* bo = (const float*)d_in[12];
    const float* g0 = (const float*)d_in[13];
    const float* b0 = (const float*)d_in[14];
    const float* g1 = (const float*)d_in[15];
    const float* b1 = (const float*)d_in[16];
    float* out = (float*)d_out;

    float *q, *k, *v, *t0, *t1;
    cudaGetSymbolAddress((void**)&q,  g_q);
    cudaGetSymbolAddress((void**)&k,  g_k);
    cudaGetSymbolAddress((void**)&v,  g_v);
    cudaGetSymbolAddress((void**)&t0, g_t0);
    cudaGetSymbolAddress((void**)&t1, g_t1);

    const float att_scale = 1.0f / sqrtf((float)DIM);

    // --- projections: q/k/v = X @ W + b   (8192x512 @ 512x512)
    {
        dim3 grid(DIM/128, MROWS/128, 1);
        gemm_nn_tc<EPI_BIAS><<<grid,256>>>(queries, Wq, q, MROWS, DIM, DIM, bq, 0);
        gemm_nn_tc<EPI_BIAS><<<grid,256>>>(keys,    Wk, k, MROWS, DIM, DIM, bk, 0);
        gemm_nn_tc<EPI_BIAS><<<grid,256>>>(keys,    Wv, v, MROWS, DIM, DIM, bv, 0);
    }

    // --- fused attention: t0 = qh + softmax(mask(QK^T)) V
    {
        cudaFuncSetAttribute(flash_tc, cudaFuncAttributeMaxDynamicSharedMemorySize,
                             FLASH_SMEM);
        dim3 grid(SEQQ/128, BATCH*NH);
        flash_tc<<<grid,256,FLASH_SMEM>>>(q, k, v, pq, pk, t0, att_scale);
    }

    // --- LN0 (in place)
    ln_k<<<MROWS, 128>>>(t0, t0, g0, b0);

    // --- t1 = t0 + relu(t0 @ Wo + bo)
    {
        dim3 grid(DIM/128, MROWS/128, 1);
        gemm_nn_tc<EPI_RELU_RESID><<<grid,256>>>(t0, Wo, t1, MROWS, DIM, DIM, bo, t0);
    }

    // --- LN1 -> out
    ln_k<<<MROWS, 128>>>(t1, out, g1, b1);
}